// round 4
// baseline (speedup 1.0000x reference)
#include <cuda_runtime.h>
#include <math.h>

#define TT 512
#define BB 128
#define DD 128
#define HH 256
#define CC 10
#define G4 1024
#define MROWS (TT*BB)
#define NCTA 128

// ---------------- static device scratch (no runtime allocation) ----------------
__device__ float g_e  [(size_t)MROWS * DD];        //  32 MB embedded inputs [t*B+b, D]
__device__ float g_XwF[(size_t)MROWS * G4];        // 256 MB x@W fwd (reused layer 2)
__device__ float g_XwB[(size_t)MROWS * G4];        // 256 MB x@W bwd (reused layer 2)
__device__ float g_seq[(size_t)MROWS * 2 * HH];    // 128 MB layer-1 output sequence
__device__ float g_state[4 * BB * HH];             // per dir: h parity buf0, buf1
__device__ unsigned g_count;                       // grid barrier arrive counter
__device__ unsigned g_epoch;                       // grid barrier epoch

// packed dual-fp32 FMA - 2x throughput of scalar 3-reg FFMA on sm_103a
__device__ __forceinline__ void ffma2(float2 &d, float2 a, float2 b) {
    asm("fma.rn.f32x2 %0, %1, %2, %0;"
        : "+l"(*reinterpret_cast<unsigned long long*>(&d))
        : "l"(*reinterpret_cast<unsigned long long*>(&a)),
          "l"(*reinterpret_cast<unsigned long long*>(&b)));
}

__device__ __forceinline__ float sigf(float x) {
    return __fdividef(1.0f, 1.0f + __expf(-x));
}
__device__ __forceinline__ float tanhfast(float x) {
    return __fdividef(2.0f, 1.0f + __expf(-2.0f * x)) - 1.0f;
}

// software grid barrier: all NCTA CTAs co-resident (1 CTA/SM)
__device__ __forceinline__ void grid_bar(unsigned &epoch) {
    __threadfence();                 // release my stores to L2 (all threads)
    __syncthreads();
    if (threadIdx.x == 0) {
        if (atomicAdd(&g_count, 1) == NCTA - 1) {
            atomicExch(&g_count, 0);
            __threadfence();
            atomicAdd(&g_epoch, 1);
        } else {
            while (*(volatile unsigned*)&g_epoch == epoch) { }
        }
        epoch++;
    }
    __syncthreads();                 // acquire: order spin before consumers
}

// ---------------- embedding gather: g_e[t*B+b, :] = emb[x[b,t], :] ----------------
__global__ void embed_k(const int* __restrict__ x, const float* __restrict__ emb) {
    int gid = blockIdx.x * blockDim.x + threadIdx.x;   // T*B*32 threads (float4 lanes)
    int r  = gid >> 5;
    int c4 = gid & 31;
    int t  = r >> 7;
    int b  = r & 127;
    int tok = x[b * TT + t];
    reinterpret_cast<float4*>(g_e)[(size_t)r * 32 + c4] =
        reinterpret_cast<const float4*>(emb)[(size_t)tok * 32 + c4];
}

// ---------------- SGEMM + bias: C[M,1024] = A[M,K] @ W[K,1024] + bias ----------------
__global__ __launch_bounds__(256) void gemm_k(int a_sel, int c_sel,
        const float* __restrict__ W, const float* __restrict__ bias, int K)
{
    const float* A = a_sel ? g_seq : g_e;
    float*       C = c_sel ? g_XwB : g_XwF;

    __shared__ __align__(16) float As[8][132];
    __shared__ __align__(16) float Bs[8][132];

    const int m0  = blockIdx.x * 128;
    const int n0  = blockIdx.y * 128;
    const int tid = threadIdx.x;
    const int ty  = tid >> 4;
    const int tx  = tid & 15;

    float2 acc[8][4];
#pragma unroll
    for (int i = 0; i < 8; ++i)
#pragma unroll
        for (int j = 0; j < 4; ++j) acc[i][j] = make_float2(0.f, 0.f);

    const int ar = tid >> 1, aq = tid & 1;
    const int bkr = tid >> 5, bc = (tid & 31) * 4;

    for (int kt = 0; kt < K; kt += 8) {
        float4 av = *reinterpret_cast<const float4*>(A + (size_t)(m0 + ar) * K + kt + aq * 4);
        float4 bv = *reinterpret_cast<const float4*>(W + (size_t)(kt + bkr) * G4 + n0 + bc);
        __syncthreads();
        As[aq * 4 + 0][ar] = av.x;
        As[aq * 4 + 1][ar] = av.y;
        As[aq * 4 + 2][ar] = av.z;
        As[aq * 4 + 3][ar] = av.w;
        *reinterpret_cast<float4*>(&Bs[bkr][bc]) = bv;
        __syncthreads();
#pragma unroll
        for (int k = 0; k < 8; ++k) {
            float4 a0 = *reinterpret_cast<const float4*>(&As[k][ty * 8]);
            float4 a1 = *reinterpret_cast<const float4*>(&As[k][ty * 8 + 4]);
            float4 b0 = *reinterpret_cast<const float4*>(&Bs[k][tx * 8]);
            float4 b1 = *reinterpret_cast<const float4*>(&Bs[k][tx * 8 + 4]);
            float av8[8] = {a0.x, a0.y, a0.z, a0.w, a1.x, a1.y, a1.z, a1.w};
            float2 bp[4] = {{b0.x, b0.y}, {b0.z, b0.w}, {b1.x, b1.y}, {b1.z, b1.w}};
#pragma unroll
            for (int i = 0; i < 8; ++i) {
                float2 aa = make_float2(av8[i], av8[i]);
#pragma unroll
                for (int j = 0; j < 4; ++j) ffma2(acc[i][j], aa, bp[j]);
            }
        }
    }

    float4 bb0 = *reinterpret_cast<const float4*>(bias + n0 + tx * 8);
    float4 bb1 = *reinterpret_cast<const float4*>(bias + n0 + tx * 8 + 4);
#pragma unroll
    for (int i = 0; i < 8; ++i) {
        size_t row = (size_t)(m0 + ty * 8 + i) * G4 + n0 + tx * 8;
        float4 o0 = make_float4(acc[i][0].x + bb0.x, acc[i][0].y + bb0.y,
                                acc[i][1].x + bb0.z, acc[i][1].y + bb0.w);
        float4 o1 = make_float4(acc[i][2].x + bb1.x, acc[i][2].y + bb1.y,
                                acc[i][3].x + bb1.z, acc[i][3].y + bb1.w);
        *reinterpret_cast<float4*>(C + row)     = o0;
        *reinterpret_cast<float4*>(C + row + 4) = o1;
    }
}

// ---------------- persistent bidirectional LSTM layer ----------------
// grid 128 CTAs (dir 2 x nt 8 x bt 8), 128 threads. U slice cached in dynamic smem
// (128KB) for all 512 steps. c is register-resident. h double-buffered in global
// with .cg loads/stores (L2 is the coherence point). One grid barrier per step.
__global__ __launch_bounds__(128) void lstm_persist_k(
        const float* __restrict__ Uf, const float* __restrict__ Ub, int write_seq)
{
    extern __shared__ float Us[];                 // [256][128] U slice
    __shared__ __align__(16) float sh[16][260];   // h tile stage

    const int bid = blockIdx.x;
    const int dir = bid >> 6;
    const int nt  = (bid >> 3) & 7;
    const int bt  = bid & 7;
    const int tid = threadIdx.x;

    const float* U  = dir ? Ub : Uf;
    const float* Xw = dir ? g_XwB : g_XwF;
    float* hbuf = g_state + (size_t)dir * 2 * BB * HH;

    // load U slice: Us[k*128 + g*32 + ln] = U[k*G4 + g*HH + nt*32 + ln]
    for (int i = tid; i < 256 * 32; i += 128) {
        int k = i >> 5;
        int col = (i & 31) * 4;
        int g = col >> 5, ln = col & 31;
        *reinterpret_cast<float4*>(&Us[k * 128 + col]) =
            *reinterpret_cast<const float4*>(U + (size_t)k * G4 + g * HH + nt * 32 + ln);
    }

    // zero my (bt, nt) patch of both h parity buffers
    for (int i = tid; i < 512; i += 128) {
        int r  = bt * 16 + (i >> 5);
        int cc = nt * 32 + (i & 31);
        __stcg(hbuf + (size_t)r * HH + cc, 0.f);
        __stcg(hbuf + (size_t)BB * HH + (size_t)r * HH + cc, 0.f);
    }

    unsigned epoch = 0;
    if (tid == 0) epoch = *(volatile unsigned*)&g_epoch;
    grid_bar(epoch);

    const int b_half = tid >> 4;          // 0..7
    const int n_grp  = tid & 15;          // 0..15
    const int nloc   = n_grp * 2;
    const int ngl    = nt * 32 + nloc;
    const int r0     = bt * 16 + b_half * 2;

    float2 cst[2] = {make_float2(0.f, 0.f), make_float2(0.f, 0.f)};

    for (int s = 0; s < TT; ++s) {
        const int t   = dir ? (TT - 1 - s) : s;
        const int par = s & 1;
        const float* hRead  = hbuf + (size_t)par * BB * HH;
        float*       hWrite = hbuf + (size_t)(par ^ 1) * BB * HH;

        // stage h tile (16 rows x 256) from L2
#pragma unroll
        for (int i = 0; i < 8; ++i) {
            int f = tid + i * 128;
            int r = f >> 6, cq = f & 63;
            *reinterpret_cast<float4*>(&sh[r][cq * 4]) =
                __ldcg(reinterpret_cast<const float4*>(
                    hRead + (size_t)(bt * 16 + r) * HH + cq * 4));
        }
        // prefetch xW for my 2 rows x 2 cols x 4 gates (DRAM latency hidden by k-loop)
        const float* xw0 = Xw + ((size_t)t * BB + r0) * G4 + ngl;
        const float* xw1 = xw0 + G4;
        float2 x0[4], x1[4];
#pragma unroll
        for (int g = 0; g < 4; ++g) {
            x0[g] = *reinterpret_cast<const float2*>(xw0 + g * HH);
            x1[g] = *reinterpret_cast<const float2*>(xw1 + g * HH);
        }
        __syncthreads();

        float2 acc[4][2];
#pragma unroll
        for (int g = 0; g < 4; ++g) {
            acc[g][0] = make_float2(0.f, 0.f);
            acc[g][1] = make_float2(0.f, 0.f);
        }

        const float* sr0 = sh[b_half * 2];
        const float* sr1 = sh[b_half * 2 + 1];
        const float* Up  = Us + nloc;

#pragma unroll 4
        for (int k4 = 0; k4 < HH; k4 += 4) {
            float4 h0v = *reinterpret_cast<const float4*>(sr0 + k4);
            float4 h1v = *reinterpret_cast<const float4*>(sr1 + k4);
            const float h0a[4] = {h0v.x, h0v.y, h0v.z, h0v.w};
            const float h1a[4] = {h1v.x, h1v.y, h1v.z, h1v.w};
#pragma unroll
            for (int kk = 0; kk < 4; ++kk) {
                const float* row = Up + (size_t)(k4 + kk) * 128;
                float2 hh0 = make_float2(h0a[kk], h0a[kk]);
                float2 hh1 = make_float2(h1a[kk], h1a[kk]);
#pragma unroll
                for (int g = 0; g < 4; ++g) {
                    float2 u2 = *reinterpret_cast<const float2*>(row + g * 32);
                    ffma2(acc[g][0], u2, hh0);
                    ffma2(acc[g][1], u2, hh1);
                }
            }
        }

        // gates + state update for 2 batch rows
#pragma unroll
        for (int bb = 0; bb < 2; ++bb) {
            const float2* xg = bb ? x1 : x0;
            float zi0 = acc[0][bb].x + xg[0].x, zi1 = acc[0][bb].y + xg[0].y;
            float zf0 = acc[1][bb].x + xg[1].x, zf1 = acc[1][bb].y + xg[1].y;
            float zg0 = acc[2][bb].x + xg[2].x, zg1 = acc[2][bb].y + xg[2].y;
            float zo0 = acc[3][bb].x + xg[3].x, zo1 = acc[3][bb].y + xg[3].y;
            float c0 = sigf(zf0) * cst[bb].x + sigf(zi0) * tanhfast(zg0);
            float c1 = sigf(zf1) * cst[bb].y + sigf(zi1) * tanhfast(zg1);
            cst[bb] = make_float2(c0, c1);
            float h0 = sigf(zo0) * tanhfast(c0);
            float h1 = sigf(zo1) * tanhfast(c1);
            int r = r0 + bb;
            __stcg(reinterpret_cast<float2*>(hWrite + (size_t)r * HH + ngl),
                   make_float2(h0, h1));
            if (write_seq)
                *reinterpret_cast<float2*>(
                    g_seq + ((size_t)t * BB + r) * (2 * HH) + dir * HH + nloc + nt * 32) =
                    make_float2(h0, h1);
        }

        grid_bar(epoch);
    }
}

// ---------------- final dense + softmax ----------------
__global__ void final_k(const float* __restrict__ Wd, const float* __restrict__ bd,
                        float* __restrict__ out)
{
    int b = blockIdx.x, lane = threadIdx.x;
    const float* hf = g_state;                    // dir0 final h (parity buf0)
    const float* hb = g_state + 2 * BB * HH;      // dir1 final h (parity buf0)
    float acc[CC];
#pragma unroll
    for (int c = 0; c < CC; ++c) acc[c] = 0.f;
    for (int k = lane; k < 2 * HH; k += 32) {
        float hv = (k < HH) ? hf[(size_t)b * HH + k] : hb[(size_t)b * HH + k - HH];
        const float* w = Wd + (size_t)k * CC;
#pragma unroll
        for (int c = 0; c < CC; ++c) acc[c] = fmaf(hv, w[c], acc[c]);
    }
#pragma unroll
    for (int c = 0; c < CC; ++c)
#pragma unroll
        for (int o = 16; o; o >>= 1) acc[c] += __shfl_down_sync(0xffffffffu, acc[c], o);
    if (lane == 0) {
        float m = -1e30f;
#pragma unroll
        for (int c = 0; c < CC; ++c) { acc[c] += bd[c]; m = fmaxf(m, acc[c]); }
        float e[CC], s = 0.f;
#pragma unroll
        for (int c = 0; c < CC; ++c) { e[c] = expf(acc[c] - m); s += e[c]; }
        float inv = 1.f / s;
#pragma unroll
        for (int c = 0; c < CC; ++c) out[b * CC + c] = e[c] * inv;
    }
}

extern "C" void kernel_launch(void* const* d_in, const int* in_sizes, int n_in,
                              void* d_out, int out_size)
{
    const int*   x   = (const int*)  d_in[0];
    const float* emb = (const float*)d_in[1];
    const float* W1f = (const float*)d_in[2];
    const float* U1f = (const float*)d_in[3];
    const float* b1f = (const float*)d_in[4];
    const float* W1b = (const float*)d_in[5];
    const float* U1b = (const float*)d_in[6];
    const float* b1b = (const float*)d_in[7];
    const float* W2f = (const float*)d_in[8];
    const float* U2f = (const float*)d_in[9];
    const float* b2f = (const float*)d_in[10];
    const float* W2b = (const float*)d_in[11];
    const float* U2b = (const float*)d_in[12];
    const float* b2b = (const float*)d_in[13];
    const float* Wd  = (const float*)d_in[14];
    const float* bd  = (const float*)d_in[15];
    float* out = (float*)d_out;

    static int smem_set = 0;
    if (!smem_set) {
        cudaFuncSetAttribute(lstm_persist_k,
                             cudaFuncAttributeMaxDynamicSharedMemorySize, 131072);
        smem_set = 1;
    }

    embed_k<<<(MROWS * 32) / 256, 256>>>(x, emb);

    dim3 gg(MROWS / 128, G4 / 128);

    // layer 1
    gemm_k<<<gg, 256>>>(0, 0, W1f, b1f, DD);
    gemm_k<<<gg, 256>>>(0, 1, W1b, b1b, DD);
    lstm_persist_k<<<NCTA, 128, 131072>>>(U1f, U1b, 1);

    // layer 2
    gemm_k<<<gg, 256>>>(1, 0, W2f, b2f, 2 * HH);
    gemm_k<<<gg, 256>>>(1, 1, W2b, b2b, 2 * HH);
    lstm_persist_k<<<NCTA, 128, 131072>>>(U2f, U2b, 0);

    final_k<<<BB, 32>>>(Wd, bd, out);
}